// round 11
// baseline (speedup 1.0000x reference)
#include <cuda_runtime.h>

// Dynamics_individual (MAK), N=8192, B=R=F=1
// d_in[0]=t (unused), d_in[1]=x [N], d_in[2]=A [N,N]
// d_out = [ f_self (N) | f_nbr (N*N) ], f_self[i]=1-x[i], f_nbr[i][j]=-x[i]*A[i][j]*x[j]
//
// FINAL (converged, measured best): compulsory 256MB read + 256MB write,
// zero reuse. Session-best measurement: kernel 75.3us, DRAM 81.1% (6422 GB/s)
// = the B300 interleaved r+w DRAM ceiling (invariant across MLP shape, vector
// width, launch geometry, cache hints). Config: TPB=256, block = half row
// (row index uniform per block), QPT=4 front-batched LDG.128 (MLP=4),
// .cs streaming hints both directions, regs=32, occ ~83%.

#define NDIM 8192u
#define QUADS_PER_ROW 2048u          // N/4
#define TPB 256u
#define QPT 4u
#define QUADS_PER_BLOCK (TPB * QPT)  // 1024 = half a row

__global__ void __launch_bounds__(256) dyn_mak_kernel(
    const float* __restrict__ x,
    const float* __restrict__ A,
    float* __restrict__ out)
{
    const unsigned i = blockIdx.x >> 1;                   // row, uniform per block
    const unsigned half = (blockIdx.x & 1u) * QUADS_PER_BLOCK;
    const unsigned base = i * QUADS_PER_ROW + half + threadIdx.x;

    const float4* __restrict__ A4 = reinterpret_cast<const float4*>(A);
    const float4* __restrict__ x4 = reinterpret_cast<const float4*>(x);
    float4* __restrict__ fnbr = reinterpret_cast<float4*>(out + NDIM);

    const float s = -__ldg(&x[i]);                        // uniform scalar

    // Front-batched: 4 independent LDG.128 in flight per thread.
    float4 a[QPT];
#pragma unroll
    for (int k = 0; k < (int)QPT; k++)
        a[k] = __ldcs(&A4[base + (unsigned)k * TPB]);

#pragma unroll
    for (int k = 0; k < (int)QPT; k++) {
        const unsigned j4 = half + threadIdx.x + (unsigned)k * TPB; // col quad
        const float4 xj = x4[j4];                                   // L1-resident
        float4 r;
        r.x = s * a[k].x * xj.x;
        r.y = s * a[k].y * xj.y;
        r.z = s * a[k].z * xj.z;
        r.w = s * a[k].w * xj.w;
        __stcs(&fnbr[base + (unsigned)k * TPB], r);
    }

    // f_self = 1 - x : 2048 quads, handled by blocks 0 and 1 (first row).
    if (blockIdx.x < 2) {
#pragma unroll
        for (int k = 0; k < (int)QPT; k++) {
            const unsigned q = half + threadIdx.x + (unsigned)k * TPB;
            const float4 xv = x4[q];
            float4 fs;
            fs.x = 1.0f - xv.x;
            fs.y = 1.0f - xv.y;
            fs.z = 1.0f - xv.z;
            fs.w = 1.0f - xv.w;
            reinterpret_cast<float4*>(out)[q] = fs;
        }
    }
}

extern "C" void kernel_launch(void* const* d_in, const int* in_sizes, int n_in,
                              void* d_out, int out_size)
{
    (void)in_sizes; (void)n_in; (void)out_size;
    const float* x = (const float*)d_in[1];
    const float* A = (const float*)d_in[2];
    float* out = (float*)d_out;

    const unsigned blocks = NDIM * 2u;   // two half-row blocks per row = 16384
    dyn_mak_kernel<<<blocks, TPB>>>(x, A, out);
}

// round 12
// speedup vs baseline: 1.0043x; 1.0043x over previous
#include <cuda_runtime.h>

// Dynamics_individual (MAK), N=8192, B=R=F=1
// d_in[0]=t (unused), d_in[1]=x [N], d_in[2]=A [N,N]
// d_out = [ f_self (N) | f_nbr (N*N) ], f_self[i]=1-x[i], f_nbr[i][j]=-x[i]*A[i][j]*x[j]
//
// FINAL (triple-confirmed converged): compulsory 256MB read + 256MB write,
// zero reuse. Kernel 75.3-75.7us, DRAM 80-81% (6.40-6.42 TB/s) = B300
// interleaved r+w DRAM ceiling, invariant across MLP shape (1/4/8), vector
// width (128/256b), launch geometry (row, half-row, persistent), and cache
// hints. Config: TPB=256, block = half row (row index uniform per block),
// QPT=4 front-batched LDG.128 (MLP=4), .cs both directions, regs=32, occ ~83%.

#define NDIM 8192u
#define QUADS_PER_ROW 2048u          // N/4
#define TPB 256u
#define QPT 4u
#define QUADS_PER_BLOCK (TPB * QPT)  // 1024 = half a row

__global__ void __launch_bounds__(256) dyn_mak_kernel(
    const float* __restrict__ x,
    const float* __restrict__ A,
    float* __restrict__ out)
{
    const unsigned i = blockIdx.x >> 1;                   // row, uniform per block
    const unsigned half = (blockIdx.x & 1u) * QUADS_PER_BLOCK;
    const unsigned base = i * QUADS_PER_ROW + half + threadIdx.x;

    const float4* __restrict__ A4 = reinterpret_cast<const float4*>(A);
    const float4* __restrict__ x4 = reinterpret_cast<const float4*>(x);
    float4* __restrict__ fnbr = reinterpret_cast<float4*>(out + NDIM);

    const float s = -__ldg(&x[i]);                        // uniform scalar

    // Front-batched: 4 independent LDG.128 in flight per thread.
    float4 a[QPT];
#pragma unroll
    for (int k = 0; k < (int)QPT; k++)
        a[k] = __ldcs(&A4[base + (unsigned)k * TPB]);

#pragma unroll
    for (int k = 0; k < (int)QPT; k++) {
        const unsigned j4 = half + threadIdx.x + (unsigned)k * TPB; // col quad
        const float4 xj = x4[j4];                                   // L1-resident
        float4 r;
        r.x = s * a[k].x * xj.x;
        r.y = s * a[k].y * xj.y;
        r.z = s * a[k].z * xj.z;
        r.w = s * a[k].w * xj.w;
        __stcs(&fnbr[base + (unsigned)k * TPB], r);
    }

    // f_self = 1 - x : 2048 quads, handled by blocks 0 and 1 (first row).
    if (blockIdx.x < 2) {
#pragma unroll
        for (int k = 0; k < (int)QPT; k++) {
            const unsigned q = half + threadIdx.x + (unsigned)k * TPB;
            const float4 xv = x4[q];
            float4 fs;
            fs.x = 1.0f - xv.x;
            fs.y = 1.0f - xv.y;
            fs.z = 1.0f - xv.z;
            fs.w = 1.0f - xv.w;
            reinterpret_cast<float4*>(out)[q] = fs;
        }
    }
}

extern "C" void kernel_launch(void* const* d_in, const int* in_sizes, int n_in,
                              void* d_out, int out_size)
{
    (void)in_sizes; (void)n_in; (void)out_size;
    const float* x = (const float*)d_in[1];
    const float* A = (const float*)d_in[2];
    float* out = (float*)d_out;

    const unsigned blocks = NDIM * 2u;   // two half-row blocks per row = 16384
    dyn_mak_kernel<<<blocks, TPB>>>(x, A, out);
}